// round 1
// baseline (speedup 1.0000x reference)
#include <cuda_runtime.h>

// Problem dims
#define LSEQ 32768
#define HDIM 256
#define PDIM 128
#define TCH  128                  // chunk length for the scan
#define NCHUNK (LSEQ / TCH)       // 256

// -------- device scratch (static: no runtime allocation allowed) ----------
__device__ float  g_W1[HDIM * 2 * PDIM];     // (K=H) x (N=2P): B_bar re/im interleaved
__device__ float  g_W2[2 * PDIM * HDIM];     // (K=2P) x (N=H): [2Cre; -2Cim]
__device__ float2 g_lam[PDIM];               // lambda_bar
__device__ float2 g_lamT[PDIM];              // lambda_bar^T
__device__ float2 g_lampow[TCH * PDIM];      // g_lampow[t*P+p] = lambda^(t+1)
__device__ float  g_Bu[LSEQ * 2 * PDIM];     // 32 MB: Bu, then x (in place)
__device__ float2 g_carry[NCHUNK * PDIM];
__device__ float2 g_pfx[NCHUNK * PDIM];

// ---------------------------------------------------------------------------
// Prep: lambda_bar, B_bar -> W1, C -> W2, per-step lambda powers
// grid = (PDIM), block = (HDIM)
// ---------------------------------------------------------------------------
__global__ void prep_kernel(const float* __restrict__ Lre,
                            const float* __restrict__ Lim,
                            const float* __restrict__ B,
                            const float* __restrict__ C,
                            const float* __restrict__ logstep) {
    const int p = blockIdx.x;
    const int h = threadIdx.x;

    const float step = expf(logstep[p]);
    const float lr = Lre[p], li = Lim[p];
    const float ar = lr * step, ai = li * step;

    float s, c;
    const float mag = expf(ar);
    sincosf(ai, &s, &c);
    const float lam_re = mag * c, lam_im = mag * s;

    // f = (lambda_bar - 1) / Lambda   (complex division)
    const float dr = lam_re - 1.0f, di = lam_im;
    const float inv_den = 1.0f / (lr * lr + li * li);
    const float fr = (dr * lr + di * li) * inv_den;
    const float fi = (di * lr - dr * li) * inv_den;

    // B_bar[p,h] = f * B_tilde[p,h]
    const float b0 = B[(p * HDIM + h) * 2 + 0];
    const float b1 = B[(p * HDIM + h) * 2 + 1];
    g_W1[h * (2 * PDIM) + 2 * p + 0] = fr * b0 - fi * b1;
    g_W1[h * (2 * PDIM) + 2 * p + 1] = fr * b1 + fi * b0;

    // W2 rows: 2*C_re at k=2p, -2*C_im at k=2p+1
    const float c0 = C[(h * PDIM + p) * 2 + 0];
    const float c1 = C[(h * PDIM + p) * 2 + 1];
    g_W2[(2 * p + 0) * HDIM + h] =  2.0f * c0;
    g_W2[(2 * p + 1) * HDIM + h] = -2.0f * c1;

    if (h == 0) g_lam[p] = make_float2(lam_re, lam_im);

    if (h < TCH) {
        const float t = (float)(h + 1);
        float ss, cc;
        const float m = expf(ar * t);
        sincosf(ai * t, &ss, &cc);
        float2 pw = make_float2(m * cc, m * ss);
        g_lampow[h * PDIM + p] = pw;
        if (h == TCH - 1) g_lamT[p] = pw;   // lambda^T
    }
}

// ---------------------------------------------------------------------------
// SGEMM: M=LSEQ, N=256, K=256, BM=BN=128, BK=8, 256 threads, 8x8 per thread.
// MODE 0: A = u,     B = g_W1, out = g_Bu
// MODE 1: A = g_Bu,  B = g_W2, out = y, epilogue adds D[h]*u[l,h]
// ---------------------------------------------------------------------------
template <int MODE>
__global__ __launch_bounds__(256)
void sgemm_kernel(const float* __restrict__ u,
                  float* __restrict__ y,
                  const float* __restrict__ Dv) {
    constexpr int BK = 8;
    __shared__ float As[BK][128];
    __shared__ float Bs[BK][128];

    const float* Aglob = (MODE == 0) ? u : g_Bu;
    const float* Bglob = (MODE == 0) ? g_W1 : g_W2;
    float* Cglob = (MODE == 0) ? g_Bu : y;

    const int cCol = blockIdx.x;   // 0..1
    const int cRow = blockIdx.y;   // 0..255

    const float* A = Aglob + (size_t)cRow * 128 * 256;
    const float* Bp = Bglob + cCol * 128;
    float* Cp = Cglob + (size_t)cRow * 128 * 256 + cCol * 128;

    const int tid = threadIdx.x;
    const int trow = tid >> 4;          // 0..15
    const int tcol = tid & 15;          // 0..15
    const int aRow = tid >> 1;          // 0..127
    const int aCol = (tid & 1) << 2;    // 0 or 4
    const int bRow = tid >> 5;          // 0..7
    const int bCol = (tid & 31) << 2;   // 0..124

    float acc[8][8];
#pragma unroll
    for (int i = 0; i < 8; i++)
#pragma unroll
        for (int j = 0; j < 8; j++) acc[i][j] = 0.0f;

    for (int k0 = 0; k0 < 256; k0 += BK) {
        const float4 av = *reinterpret_cast<const float4*>(A + aRow * 256 + k0 + aCol);
        As[aCol + 0][aRow] = av.x;
        As[aCol + 1][aRow] = av.y;
        As[aCol + 2][aRow] = av.z;
        As[aCol + 3][aRow] = av.w;
        *reinterpret_cast<float4*>(&Bs[bRow][bCol]) =
            *reinterpret_cast<const float4*>(Bp + (k0 + bRow) * 256 + bCol);
        __syncthreads();
#pragma unroll
        for (int k = 0; k < BK; k++) {
            const float4 a0 = *reinterpret_cast<const float4*>(&As[k][trow * 8]);
            const float4 a1 = *reinterpret_cast<const float4*>(&As[k][trow * 8 + 4]);
            const float4 b0 = *reinterpret_cast<const float4*>(&Bs[k][tcol * 8]);
            const float4 b1 = *reinterpret_cast<const float4*>(&Bs[k][tcol * 8 + 4]);
            const float a[8] = {a0.x, a0.y, a0.z, a0.w, a1.x, a1.y, a1.z, a1.w};
            const float b[8] = {b0.x, b0.y, b0.z, b0.w, b1.x, b1.y, b1.z, b1.w};
#pragma unroll
            for (int i = 0; i < 8; i++)
#pragma unroll
                for (int j = 0; j < 8; j++) acc[i][j] += a[i] * b[j];
        }
        __syncthreads();
    }

#pragma unroll
    for (int i = 0; i < 8; i++) {
        const int row = trow * 8 + i;
#pragma unroll
        for (int j4 = 0; j4 < 2; j4++) {
            const int col = tcol * 8 + j4 * 4;
            float4 o;
            o.x = acc[i][j4 * 4 + 0];
            o.y = acc[i][j4 * 4 + 1];
            o.z = acc[i][j4 * 4 + 2];
            o.w = acc[i][j4 * 4 + 3];
            if (MODE == 1) {
                const float* Up = u + (size_t)cRow * 128 * 256 + cCol * 128;
                const float4 u4 = *reinterpret_cast<const float4*>(Up + row * 256 + col);
                const int gcol = cCol * 128 + col;
                o.x += __ldg(Dv + gcol + 0) * u4.x;
                o.y += __ldg(Dv + gcol + 1) * u4.y;
                o.z += __ldg(Dv + gcol + 2) * u4.z;
                o.w += __ldg(Dv + gcol + 3) * u4.w;
            }
            *reinterpret_cast<float4*>(Cp + row * 256 + col) = o;
        }
    }
}

// ---------------------------------------------------------------------------
// Local scan within each chunk (in place over g_Bu), emit per-chunk carry.
// grid = NCHUNK, block = PDIM (one thread per state)
// ---------------------------------------------------------------------------
__global__ __launch_bounds__(PDIM)
void scan_local_kernel() {
    const int chunk = blockIdx.x;
    const int p = threadIdx.x;
    const float2 lam = g_lam[p];
    float2 x = make_float2(0.0f, 0.0f);
    float2* bu = reinterpret_cast<float2*>(g_Bu) + (size_t)chunk * TCH * PDIM + p;
#pragma unroll 4
    for (int t = 0; t < TCH; t++) {
        const float2 b = bu[t * PDIM];
        const float nr = lam.x * x.x - lam.y * x.y + b.x;
        const float ni = lam.x * x.y + lam.y * x.x + b.y;
        x.x = nr;
        x.y = ni;
        bu[t * PDIM] = x;
    }
    g_carry[chunk * PDIM + p] = x;
}

// ---------------------------------------------------------------------------
// Sequential carry scan across chunks (exclusive prefix of chunk states).
// grid = 1, block = PDIM
// ---------------------------------------------------------------------------
__global__ __launch_bounds__(PDIM)
void carry_scan_kernel() {
    const int p = threadIdx.x;
    const float2 lt = g_lamT[p];
    float2 c = make_float2(0.0f, 0.0f);
    for (int j = 0; j < NCHUNK; j++) {
        g_pfx[j * PDIM + p] = c;
        const float2 b = g_carry[j * PDIM + p];
        const float nr = lt.x * c.x - lt.y * c.y + b.x;
        const float ni = lt.x * c.y + lt.y * c.x + b.y;
        c.x = nr;
        c.y = ni;
    }
}

// ---------------------------------------------------------------------------
// Fix-up: x[l,p] += lambda^(tloc+1) * pfx[chunk,p]
// grid = LSEQ*PDIM/256, block = 256
// ---------------------------------------------------------------------------
__global__ __launch_bounds__(256)
void fix_kernel() {
    const int idx = blockIdx.x * 256 + threadIdx.x;  // over LSEQ*PDIM
    const int p = idx & (PDIM - 1);
    const int l = idx >> 7;                          // PDIM = 128
    const int chunk = l / TCH;
    const int tloc = l % TCH;
    const float2 c = g_pfx[chunk * PDIM + p];
    const float2 pw = g_lampow[tloc * PDIM + p];
    float2* xp = reinterpret_cast<float2*>(g_Bu) + idx;
    float2 x = *xp;
    x.x += pw.x * c.x - pw.y * c.y;
    x.y += pw.x * c.y + pw.y * c.x;
    *xp = x;
}

// ---------------------------------------------------------------------------
extern "C" void kernel_launch(void* const* d_in, const int* in_sizes, int n_in,
                              void* d_out, int out_size) {
    const float* Lre     = (const float*)d_in[0];
    const float* Lim     = (const float*)d_in[1];
    const float* B       = (const float*)d_in[2];
    const float* C       = (const float*)d_in[3];
    const float* D       = (const float*)d_in[4];
    const float* logstep = (const float*)d_in[5];
    const float* u       = (const float*)d_in[6];
    float* y = (float*)d_out;

    prep_kernel<<<PDIM, HDIM>>>(Lre, Lim, B, C, logstep);

    dim3 grid_gemm(2, LSEQ / 128);
    sgemm_kernel<0><<<grid_gemm, 256>>>(u, nullptr, nullptr);

    scan_local_kernel<<<NCHUNK, PDIM>>>();
    carry_scan_kernel<<<1, PDIM>>>();
    fix_kernel<<<(LSEQ * PDIM) / 256, 256>>>();

    sgemm_kernel<1><<<grid_gemm, 256>>>(u, y, D);
}

// round 2
// speedup vs baseline: 1.2112x; 1.2112x over previous
#include <cuda_runtime.h>

// Problem dims
#define LSEQ 32768
#define HDIM 256
#define PDIM 128
#define TCH  64                   // chunk length for the scan
#define NCHUNK (LSEQ / TCH)       // 512

// -------- device scratch (static: no runtime allocation allowed) ----------
__device__ float  g_W1[HDIM * 2 * PDIM];     // (K=H) x (N=2P): B_bar re/im interleaved
__device__ float  g_W2[2 * PDIM * HDIM];     // (K=2P) x (N=H): [2Cre; -2Cim]
__device__ float2 g_lam[PDIM];               // lambda_bar
__device__ float2 g_lamT[PDIM];              // lambda_bar^TCH
__device__ float2 g_lampow[TCH * PDIM];      // g_lampow[t*P+p] = lambda^(t+1)
__device__ float  g_Bu[LSEQ * 2 * PDIM];     // 32 MB: Bu, then x (in place)
__device__ float2 g_carry[NCHUNK * PDIM];
__device__ float2 g_pfx[NCHUNK * PDIM];

// ---------------------------------------------------------------------------
// Prep: lambda_bar, B_bar -> W1, C -> W2, per-step lambda powers
// grid = (PDIM), block = (HDIM)
// ---------------------------------------------------------------------------
__global__ void prep_kernel(const float* __restrict__ Lre,
                            const float* __restrict__ Lim,
                            const float* __restrict__ B,
                            const float* __restrict__ C,
                            const float* __restrict__ logstep) {
    const int p = blockIdx.x;
    const int h = threadIdx.x;

    const float step = expf(logstep[p]);
    const float lr = Lre[p], li = Lim[p];
    const float ar = lr * step, ai = li * step;

    float s, c;
    const float mag = expf(ar);
    sincosf(ai, &s, &c);
    const float lam_re = mag * c, lam_im = mag * s;

    // f = (lambda_bar - 1) / Lambda   (complex division)
    const float dr = lam_re - 1.0f, di = lam_im;
    const float inv_den = 1.0f / (lr * lr + li * li);
    const float fr = (dr * lr + di * li) * inv_den;
    const float fi = (di * lr - dr * li) * inv_den;

    // B_bar[p,h] = f * B_tilde[p,h]
    const float b0 = B[(p * HDIM + h) * 2 + 0];
    const float b1 = B[(p * HDIM + h) * 2 + 1];
    g_W1[h * (2 * PDIM) + 2 * p + 0] = fr * b0 - fi * b1;
    g_W1[h * (2 * PDIM) + 2 * p + 1] = fr * b1 + fi * b0;

    // W2 rows: 2*C_re at k=2p, -2*C_im at k=2p+1
    const float c0 = C[(h * PDIM + p) * 2 + 0];
    const float c1 = C[(h * PDIM + p) * 2 + 1];
    g_W2[(2 * p + 0) * HDIM + h] =  2.0f * c0;
    g_W2[(2 * p + 1) * HDIM + h] = -2.0f * c1;

    if (h == 0) g_lam[p] = make_float2(lam_re, lam_im);

    if (h < TCH) {
        const float t = (float)(h + 1);
        float ss, cc;
        const float m = expf(ar * t);
        sincosf(ai * t, &ss, &cc);
        float2 pw = make_float2(m * cc, m * ss);
        g_lampow[h * PDIM + p] = pw;
        if (h == TCH - 1) g_lamT[p] = pw;   // lambda^TCH
    }
}

// ---------------------------------------------------------------------------
// SGEMM: M=LSEQ, N=256, K=256, BM=BN=128, BK=8, 256 threads, 8x8 per thread.
// MODE 0: A = u,     B = g_W1, out = g_Bu
// MODE 1: A = g_Bu,  B = g_W2, out = y, epilogue adds D[h]*u[l,h]
// ---------------------------------------------------------------------------
template <int MODE>
__global__ __launch_bounds__(256)
void sgemm_kernel(const float* __restrict__ u,
                  float* __restrict__ y,
                  const float* __restrict__ Dv) {
    constexpr int BK = 8;
    __shared__ float As[BK][128];
    __shared__ float Bs[BK][128];

    const float* Aglob = (MODE == 0) ? u : g_Bu;
    const float* Bglob = (MODE == 0) ? g_W1 : g_W2;
    float* Cglob = (MODE == 0) ? g_Bu : y;

    const int cCol = blockIdx.x;   // 0..1
    const int cRow = blockIdx.y;   // 0..255

    const float* A = Aglob + (size_t)cRow * 128 * 256;
    const float* Bp = Bglob + cCol * 128;
    float* Cp = Cglob + (size_t)cRow * 128 * 256 + cCol * 128;

    const int tid = threadIdx.x;
    const int trow = tid >> 4;          // 0..15
    const int tcol = tid & 15;          // 0..15
    const int aRow = tid >> 1;          // 0..127
    const int aCol = (tid & 1) << 2;    // 0 or 4
    const int bRow = tid >> 5;          // 0..7
    const int bCol = (tid & 31) << 2;   // 0..124

    float acc[8][8];
#pragma unroll
    for (int i = 0; i < 8; i++)
#pragma unroll
        for (int j = 0; j < 8; j++) acc[i][j] = 0.0f;

    for (int k0 = 0; k0 < 256; k0 += BK) {
        const float4 av = *reinterpret_cast<const float4*>(A + aRow * 256 + k0 + aCol);
        As[aCol + 0][aRow] = av.x;
        As[aCol + 1][aRow] = av.y;
        As[aCol + 2][aRow] = av.z;
        As[aCol + 3][aRow] = av.w;
        *reinterpret_cast<float4*>(&Bs[bRow][bCol]) =
            *reinterpret_cast<const float4*>(Bp + (k0 + bRow) * 256 + bCol);
        __syncthreads();
#pragma unroll
        for (int k = 0; k < BK; k++) {
            const float4 a0 = *reinterpret_cast<const float4*>(&As[k][trow * 8]);
            const float4 a1 = *reinterpret_cast<const float4*>(&As[k][trow * 8 + 4]);
            const float4 b0 = *reinterpret_cast<const float4*>(&Bs[k][tcol * 8]);
            const float4 b1 = *reinterpret_cast<const float4*>(&Bs[k][tcol * 8 + 4]);
            const float a[8] = {a0.x, a0.y, a0.z, a0.w, a1.x, a1.y, a1.z, a1.w};
            const float b[8] = {b0.x, b0.y, b0.z, b0.w, b1.x, b1.y, b1.z, b1.w};
#pragma unroll
            for (int i = 0; i < 8; i++)
#pragma unroll
                for (int j = 0; j < 8; j++) acc[i][j] += a[i] * b[j];
        }
        __syncthreads();
    }

#pragma unroll
    for (int i = 0; i < 8; i++) {
        const int row = trow * 8 + i;
#pragma unroll
        for (int j4 = 0; j4 < 2; j4++) {
            const int col = tcol * 8 + j4 * 4;
            float4 o;
            o.x = acc[i][j4 * 4 + 0];
            o.y = acc[i][j4 * 4 + 1];
            o.z = acc[i][j4 * 4 + 2];
            o.w = acc[i][j4 * 4 + 3];
            if (MODE == 1) {
                const float* Up = u + (size_t)cRow * 128 * 256 + cCol * 128;
                const float4 u4 = *reinterpret_cast<const float4*>(Up + row * 256 + col);
                const int gcol = cCol * 128 + col;
                o.x += __ldg(Dv + gcol + 0) * u4.x;
                o.y += __ldg(Dv + gcol + 1) * u4.y;
                o.z += __ldg(Dv + gcol + 2) * u4.z;
                o.w += __ldg(Dv + gcol + 3) * u4.w;
            }
            *reinterpret_cast<float4*>(Cp + row * 256 + col) = o;
        }
    }
}

// ---------------------------------------------------------------------------
// Local scan within each chunk (in place over g_Bu), emit per-chunk carry.
// grid = NCHUNK, block = PDIM (one thread per state)
// ---------------------------------------------------------------------------
__global__ __launch_bounds__(PDIM)
void scan_local_kernel() {
    const int chunk = blockIdx.x;
    const int p = threadIdx.x;
    const float2 lam = g_lam[p];
    float2 x = make_float2(0.0f, 0.0f);
    float2* bu = reinterpret_cast<float2*>(g_Bu) + (size_t)chunk * TCH * PDIM + p;
#pragma unroll 8
    for (int t = 0; t < TCH; t++) {
        const float2 b = bu[t * PDIM];
        const float nr = lam.x * x.x - lam.y * x.y + b.x;
        const float ni = lam.x * x.y + lam.y * x.x + b.y;
        x.x = nr;
        x.y = ni;
        bu[t * PDIM] = x;
    }
    g_carry[chunk * PDIM + p] = x;
}

// ---------------------------------------------------------------------------
// Parallel carry scan across chunks: Kogge-Stone over NCHUNK elements per
// state. Each element is the affine op x -> a*x + b with a = lambda^TCH,
// b = carry[chunk]. Exclusive prefix -> g_pfx.
// grid = PDIM blocks (one per state), block = NCHUNK threads.
// ---------------------------------------------------------------------------
__global__ __launch_bounds__(NCHUNK)
void carry_scan_par_kernel() {
    const int p = blockIdx.x;
    const int j = threadIdx.x;
    __shared__ float2 sa[2][NCHUNK];
    __shared__ float2 sb[2][NCHUNK];

    float2 a = g_lamT[p];
    float2 b = g_carry[j * PDIM + p];
    int cur = 0;
    sa[0][j] = a;
    sb[0][j] = b;
    __syncthreads();

#pragma unroll
    for (int s = 1; s < NCHUNK; s <<= 1) {
        float2 na = a, nb = b;
        if (j >= s) {
            const float2 pa = sa[cur][j - s];
            const float2 pb = sb[cur][j - s];
            // compose: current after previous: (a*pa, a*pb + b)
            na.x = a.x * pa.x - a.y * pa.y;
            na.y = a.x * pa.y + a.y * pa.x;
            nb.x = a.x * pb.x - a.y * pb.y + b.x;
            nb.y = a.x * pb.y + a.y * pb.x + b.y;
        }
        cur ^= 1;
        sa[cur][j] = na;
        sb[cur][j] = nb;
        a = na;
        b = nb;
        __syncthreads();
    }

    // inclusive state after chunk j is sb[cur][j]; exclusive prefix = [j-1]
    g_pfx[j * PDIM + p] = (j == 0) ? make_float2(0.0f, 0.0f) : sb[cur][j - 1];
}

// ---------------------------------------------------------------------------
// Fix-up: x[l,p] += lambda^(tloc+1) * pfx[chunk,p]
// grid = LSEQ*PDIM/256, block = 256
// ---------------------------------------------------------------------------
__global__ __launch_bounds__(256)
void fix_kernel() {
    const int idx = blockIdx.x * 256 + threadIdx.x;  // over LSEQ*PDIM
    const int p = idx & (PDIM - 1);
    const int l = idx >> 7;                          // PDIM = 128
    const int chunk = l / TCH;
    const int tloc = l & (TCH - 1);
    const float2 c = g_pfx[chunk * PDIM + p];
    const float2 pw = g_lampow[tloc * PDIM + p];
    float2* xp = reinterpret_cast<float2*>(g_Bu) + idx;
    float2 x = *xp;
    x.x += pw.x * c.x - pw.y * c.y;
    x.y += pw.x * c.y + pw.y * c.x;
    *xp = x;
}

// ---------------------------------------------------------------------------
extern "C" void kernel_launch(void* const* d_in, const int* in_sizes, int n_in,
                              void* d_out, int out_size) {
    const float* Lre     = (const float*)d_in[0];
    const float* Lim     = (const float*)d_in[1];
    const float* B       = (const float*)d_in[2];
    const float* C       = (const float*)d_in[3];
    const float* D       = (const float*)d_in[4];
    const float* logstep = (const float*)d_in[5];
    const float* u       = (const float*)d_in[6];
    float* y = (float*)d_out;

    prep_kernel<<<PDIM, HDIM>>>(Lre, Lim, B, C, logstep);

    dim3 grid_gemm(2, LSEQ / 128);
    sgemm_kernel<0><<<grid_gemm, 256>>>(u, nullptr, nullptr);

    scan_local_kernel<<<NCHUNK, PDIM>>>();
    carry_scan_par_kernel<<<PDIM, NCHUNK>>>();
    fix_kernel<<<(LSEQ * PDIM) / 256, 256>>>();

    sgemm_kernel<1><<<grid_gemm, 256>>>(u, y, D);
}

// round 4
// speedup vs baseline: 2.5727x; 2.1240x over previous
#include <cuda_runtime.h>
#include <cuda_bf16.h>
#include <cstdint>

// Problem dims
#define LSEQ 32768
#define HDIM 256
#define PDIM 128
#define TCH  64                   // scan chunk length
#define NCHUNK (LSEQ / TCH)       // 512

// ---------------------------------------------------------------------------
__device__ __forceinline__ uint32_t smem_u32(const void* p) {
    uint32_t a;
    asm("{ .reg .u64 t; cvta.to.shared.u64 t, %1; cvt.u32.u64 %0, t; }" : "=r"(a) : "l"(p));
    return a;
}
__device__ __forceinline__ void ldsm_x4(uint32_t (&r)[4], uint32_t addr) {
    asm volatile("ldmatrix.sync.aligned.m8n8.x4.shared.b16 {%0,%1,%2,%3}, [%4];"
        : "=r"(r[0]), "=r"(r[1]), "=r"(r[2]), "=r"(r[3]) : "r"(addr));
}
__device__ __forceinline__ void ldsm_x2(uint32_t (&r)[2], uint32_t addr) {
    asm volatile("ldmatrix.sync.aligned.m8n8.x2.shared.b16 {%0,%1}, [%2];"
        : "=r"(r[0]), "=r"(r[1]) : "r"(addr));
}
__device__ __forceinline__ void mma_bf16(float (&d)[4], const uint32_t (&a)[4],
                                         const uint32_t (&b)[2]) {
    asm volatile("mma.sync.aligned.m16n8k16.row.col.f32.bf16.bf16.f32 "
        "{%0,%1,%2,%3}, {%4,%5,%6,%7}, {%8,%9}, {%0,%1,%2,%3};"
        : "+f"(d[0]), "+f"(d[1]), "+f"(d[2]), "+f"(d[3])
        : "r"(a[0]), "r"(a[1]), "r"(a[2]), "r"(a[3]), "r"(b[0]), "r"(b[1]));
}
__device__ __forceinline__ void cp_async16(uint32_t dst, const void* src) {
    asm volatile("cp.async.cg.shared.global [%0], [%1], 16;" :: "r"(dst), "l"(src));
}
#define CP_COMMIT() asm volatile("cp.async.commit_group;")
#define CP_WAIT0()  asm volatile("cp.async.wait_group 0;")

// -------- device scratch (static) ------------------------------------------
__device__ __align__(128) __nv_bfloat16 g_W1h[256 * 256];  // GEMM1 B: [n=2p+ri][k=h]
__device__ __align__(128) __nv_bfloat16 g_W1l[256 * 256];
__device__ __align__(128) __nv_bfloat16 g_W2h[256 * 256];  // GEMM2 B: [n=h][k=2p+ri]
__device__ __align__(128) __nv_bfloat16 g_W2l[256 * 256];
__device__ float2 g_lam[PDIM];
__device__ float2 g_lamT[PDIM];
__device__ float2 g_lampow[TCH * PDIM];                    // lambda^(t+1)
__device__ __align__(128) float g_Bu[LSEQ * 2 * PDIM];     // 32 MB: x_local
__device__ float2 g_carry[NCHUNK * PDIM];
__device__ float2 g_pfx[NCHUNK * PDIM];

// ---------------------------------------------------------------------------
// Prep
// ---------------------------------------------------------------------------
__global__ void prep_kernel(const float* __restrict__ Lre,
                            const float* __restrict__ Lim,
                            const float* __restrict__ B,
                            const float* __restrict__ C,
                            const float* __restrict__ logstep) {
    const int p = blockIdx.x;
    const int h = threadIdx.x;

    const float step = expf(logstep[p]);
    const float lr = Lre[p], li = Lim[p];
    const float ar = lr * step, ai = li * step;

    float s, c;
    const float mag = expf(ar);
    sincosf(ai, &s, &c);
    const float lam_re = mag * c, lam_im = mag * s;

    const float dr = lam_re - 1.0f, di = lam_im;
    const float inv_den = 1.0f / (lr * lr + li * li);
    const float fr = (dr * lr + di * li) * inv_den;
    const float fi = (di * lr - dr * li) * inv_den;

    const float b0 = B[(p * HDIM + h) * 2 + 0];
    const float b1 = B[(p * HDIM + h) * 2 + 1];
    const float w1r = fr * b0 - fi * b1;
    const float w1i = fr * b1 + fi * b0;
    {
        __nv_bfloat16 hh = __float2bfloat16_rn(w1r);
        g_W1h[(2 * p + 0) * 256 + h] = hh;
        g_W1l[(2 * p + 0) * 256 + h] = __float2bfloat16_rn(w1r - __bfloat162float(hh));
        hh = __float2bfloat16_rn(w1i);
        g_W1h[(2 * p + 1) * 256 + h] = hh;
        g_W1l[(2 * p + 1) * 256 + h] = __float2bfloat16_rn(w1i - __bfloat162float(hh));
    }
    const float c0 =  2.0f * C[(h * PDIM + p) * 2 + 0];
    const float c1 = -2.0f * C[(h * PDIM + p) * 2 + 1];
    {
        __nv_bfloat16 hh = __float2bfloat16_rn(c0);
        g_W2h[h * 256 + 2 * p + 0] = hh;
        g_W2l[h * 256 + 2 * p + 0] = __float2bfloat16_rn(c0 - __bfloat162float(hh));
        hh = __float2bfloat16_rn(c1);
        g_W2h[h * 256 + 2 * p + 1] = hh;
        g_W2l[h * 256 + 2 * p + 1] = __float2bfloat16_rn(c1 - __bfloat162float(hh));
    }

    if (h == 0) g_lam[p] = make_float2(lam_re, lam_im);

    if (h < TCH) {
        const float t = (float)(h + 1);
        float ss, cc;
        const float m = expf(ar * t);
        sincosf(ai * t, &ss, &cc);
        float2 pw = make_float2(m * cc, m * ss);
        g_lampow[h * PDIM + p] = pw;
        if (h == TCH - 1) g_lamT[p] = pw;
    }
}

// ---------------------------------------------------------------------------
// HMMA GEMM, M-tile 128, N-tile 128, BK=64, 8 warps (2x4), warp tile 64x32.
// bf16 3-term split for fp32-class accuracy.
// MODE 0: A=u, B=W1 -> Bu, epilogue runs local scan in SMEM, writes x_local+carry
// MODE 1: A=x_local (+ fused prefix fix), B=W2 -> y (+ D*u)
// ---------------------------------------------------------------------------
#define STAGE   65536                // Ah 16K | Al 16K | Bh 16K | Bl 16K
#define OFF_AH  0
#define OFF_AL  16384
#define OFF_BH  32768
#define OFF_BL  49152
#define XS_STRIDE 264                // floats per row in epilogue staging
#define SM_TOTAL  (128 * XS_STRIDE * 4)   // 135168 >= 2*STAGE

template <int MODE>
__global__ __launch_bounds__(256, 1)
void gemm_hmma_kernel(const float* __restrict__ u,
                      float* __restrict__ y,
                      const float* __restrict__ Dv) {
    extern __shared__ char smem[];
    const uint32_t smem_base = smem_u32(smem);
    const int tid = threadIdx.x;
    const int wid = tid >> 5;
    const int lane = tid & 31;
    const int warp_m = wid >> 2;       // 0..1
    const int warp_n = wid & 3;        // 0..3
    const int n0 = blockIdx.x * 128;
    const int m0 = blockIdx.y * 128;

    const float* Asrc = (MODE == 0) ? u : g_Bu;
    const __nv_bfloat16* Bhp = (MODE == 0) ? g_W1h : g_W2h;
    const __nv_bfloat16* Blp = (MODE == 0) ? g_W1l : g_W2l;

    float acc[16][4];
#pragma unroll
    for (int i = 0; i < 16; i++)
#pragma unroll
        for (int j = 0; j < 4; j++) acc[i][j] = 0.0f;

    float4 aReg[8];

    // ---- helpers as lambdas ----
    auto loadA = [&](int c) {
#pragma unroll
        for (int j = 0; j < 8; j++) {
            const int i4 = tid + j * 256;
            const int row = i4 >> 4;
            const int fc = (i4 & 15) << 2;
            float4 v = *reinterpret_cast<const float4*>(
                Asrc + (size_t)(m0 + row) * 256 + c * 64 + fc);
            if (MODE == 1) {
                const int l = m0 + row;
                const int pp = (c * 64 + fc) >> 1;
                const float2 pw0 = g_lampow[(l & 63) * 128 + pp];
                const float2 pw1 = g_lampow[(l & 63) * 128 + pp + 1];
                const float2 cf0 = g_pfx[(l >> 6) * 128 + pp];
                const float2 cf1 = g_pfx[(l >> 6) * 128 + pp + 1];
                v.x += pw0.x * cf0.x - pw0.y * cf0.y;
                v.y += pw0.x * cf0.y + pw0.y * cf0.x;
                v.z += pw1.x * cf1.x - pw1.y * cf1.y;
                v.w += pw1.x * cf1.y + pw1.y * cf1.x;
            }
            aReg[j] = v;
        }
    };
    auto storeA = [&](int buf) {
#pragma unroll
        for (int j = 0; j < 8; j++) {
            const int i4 = tid + j * 256;
            const int row = i4 >> 4;
            const int fc = (i4 & 15) << 2;
            const float4 v = aReg[j];
            __nv_bfloat16 h0 = __float2bfloat16_rn(v.x);
            __nv_bfloat16 h1 = __float2bfloat16_rn(v.y);
            __nv_bfloat16 h2 = __float2bfloat16_rn(v.z);
            __nv_bfloat16 h3 = __float2bfloat16_rn(v.w);
            __nv_bfloat16 l0 = __float2bfloat16_rn(v.x - __bfloat162float(h0));
            __nv_bfloat16 l1 = __float2bfloat16_rn(v.y - __bfloat162float(h1));
            __nv_bfloat16 l2 = __float2bfloat16_rn(v.z - __bfloat162float(h2));
            __nv_bfloat16 l3 = __float2bfloat16_rn(v.w - __bfloat162float(h3));
            uint2 hv, lv;
            hv.x = ((uint32_t)__bfloat16_as_ushort(h1) << 16) | __bfloat16_as_ushort(h0);
            hv.y = ((uint32_t)__bfloat16_as_ushort(h3) << 16) | __bfloat16_as_ushort(h2);
            lv.x = ((uint32_t)__bfloat16_as_ushort(l1) << 16) | __bfloat16_as_ushort(l0);
            lv.y = ((uint32_t)__bfloat16_as_ushort(l3) << 16) | __bfloat16_as_ushort(l2);
            const uint32_t off = (uint32_t)(buf * STAGE + row * 128 +
                                 (((fc >> 3) ^ (row & 7)) << 4) + ((fc & 4) << 1));
            *reinterpret_cast<uint2*>(smem + OFF_AH + off) = hv;
            *reinterpret_cast<uint2*>(smem + OFF_AL + off) = lv;
        }
    };
    auto issueB = [&](int c, int buf) {
#pragma unroll
        for (int j = 0; j < 4; j++) {
            const int i = tid + j * 256;
            const int row = i >> 3;
            const int un = i & 7;
            const uint32_t off = (uint32_t)(buf * STAGE + row * 128 +
                                 ((un ^ (row & 7)) << 4));
            const size_t gsrc = (size_t)(n0 + row) * 256 + c * 64 + un * 8;
            cp_async16(smem_base + OFF_BH + off, Bhp + gsrc);
            cp_async16(smem_base + OFF_BL + off, Blp + gsrc);
        }
        CP_COMMIT();
    };
    auto compute = [&](int buf) {
        const uint32_t ahb = smem_base + OFF_AH + buf * STAGE;
        const uint32_t alb = smem_base + OFF_AL + buf * STAGE;
        const uint32_t bhb = smem_base + OFF_BH + buf * STAGE;
        const uint32_t blb = smem_base + OFF_BL + buf * STAGE;
#pragma unroll
        for (int kk = 0; kk < 4; kk++) {
            uint32_t afh[4][4], afl[4][4], bfh[4][2], bfl[4][2];
#pragma unroll
            for (int mi = 0; mi < 4; mi++) {
                const int row = warp_m * 64 + mi * 16 + (lane & 7) + ((lane >> 3) & 1) * 8;
                const int kc = kk * 2 + (lane >> 4);           // 16B chunk index
                const uint32_t off = (uint32_t)(row * 128 + ((kc ^ (row & 7)) << 4));
                ldsm_x4(afh[mi], ahb + off);
                ldsm_x4(afl[mi], alb + off);
            }
#pragma unroll
            for (int ni = 0; ni < 4; ni++) {
                const int row = warp_n * 32 + ni * 8 + (lane & 7);
                const int kc = kk * 2 + ((lane >> 3) & 1);
                const uint32_t off = (uint32_t)(row * 128 + ((kc ^ (row & 7)) << 4));
                ldsm_x2(bfh[ni], bhb + off);
                ldsm_x2(bfl[ni], blb + off);
            }
#pragma unroll
            for (int mi = 0; mi < 4; mi++)
#pragma unroll
                for (int ni = 0; ni < 4; ni++) {
                    mma_bf16(acc[mi * 4 + ni], afh[mi], bfh[ni]);
                    mma_bf16(acc[mi * 4 + ni], afl[mi], bfh[ni]);
                    mma_bf16(acc[mi * 4 + ni], afh[mi], bfl[ni]);
                }
        }
    };

    // ---- pipelined mainloop over 4 K-chunks ----
    issueB(0, 0);
    loadA(0);
    for (int c = 0; c < 4; c++) {
        const int buf = c & 1;
        storeA(buf);
        CP_WAIT0();
        __syncthreads();
        if (c < 3) {
            issueB(c + 1, buf ^ 1);
            loadA(c + 1);
        }
        compute(buf);
    }
    __syncthreads();   // before SMEM reuse

    if (MODE == 0) {
        // ---- epilogue: stage Bu tile in SMEM, local scan, write x_local ----
        float* xs = reinterpret_cast<float*>(smem);
#pragma unroll
        for (int mi = 0; mi < 4; mi++) {
            const int r0 = warp_m * 64 + mi * 16 + (lane >> 2);
#pragma unroll
            for (int ni = 0; ni < 4; ni++) {
                const int cc = warp_n * 32 + ni * 8 + (lane & 3) * 2;
                const float* a = acc[mi * 4 + ni];
                *reinterpret_cast<float2*>(xs + r0 * XS_STRIDE + cc) = make_float2(a[0], a[1]);
                *reinterpret_cast<float2*>(xs + (r0 + 8) * XS_STRIDE + cc) = make_float2(a[2], a[3]);
            }
        }
        __syncthreads();

        if (tid < 128) {
            const int half = tid >> 6;
            const int pl = tid & 63;
            const int pg = (n0 >> 1) + pl;
            const float2 lam = g_lam[pg];
            float2 x = make_float2(0.0f, 0.0f);
            float* base = xs + (half * 64) * XS_STRIDE + 2 * pl;
#pragma unroll 4
            for (int t = 0; t < 64; t++) {
                float2 b = *reinterpret_cast<float2*>(base + t * XS_STRIDE);
                const float nr = lam.x * x.x - lam.y * x.y + b.x;
                const float ni2 = lam.x * x.y + lam.y * x.x + b.y;
                x.x = nr; x.y = ni2;
                *reinterpret_cast<float2*>(base + t * XS_STRIDE) = x;
            }
            g_carry[((m0 >> 6) + half) * 128 + pg] = x;
        }
        __syncthreads();

#pragma unroll
        for (int j = 0; j < 16; j++) {
            const int i4 = tid + j * 256;
            const int r = i4 >> 5;
            const int c4 = i4 & 31;
            const float4 v = *reinterpret_cast<const float4*>(xs + r * XS_STRIDE + c4 * 4);
            *reinterpret_cast<float4*>(g_Bu + (size_t)(m0 + r) * 256 + n0 + c4 * 4) = v;
        }
    } else {
        // ---- epilogue: y = acc + D*u, direct ----
#pragma unroll
        for (int mi = 0; mi < 4; mi++) {
            const int r0 = m0 + warp_m * 64 + mi * 16 + (lane >> 2);
#pragma unroll
            for (int ni = 0; ni < 4; ni++) {
                const int gc = n0 + warp_n * 32 + ni * 8 + (lane & 3) * 2;
                const float d0 = __ldg(Dv + gc), d1 = __ldg(Dv + gc + 1);
                const float* a = acc[mi * 4 + ni];
                const float2 u0 = *reinterpret_cast<const float2*>(u + (size_t)r0 * 256 + gc);
                const float2 u1 = *reinterpret_cast<const float2*>(u + (size_t)(r0 + 8) * 256 + gc);
                *reinterpret_cast<float2*>(y + (size_t)r0 * 256 + gc) =
                    make_float2(a[0] + d0 * u0.x, a[1] + d1 * u0.y);
                *reinterpret_cast<float2*>(y + (size_t)(r0 + 8) * 256 + gc) =
                    make_float2(a[2] + d0 * u1.x, a[3] + d1 * u1.y);
            }
        }
    }
}

// ---------------------------------------------------------------------------
// Parallel carry scan across chunks (Kogge-Stone), exclusive prefix -> g_pfx.
// ---------------------------------------------------------------------------
__global__ __launch_bounds__(NCHUNK)
void carry_scan_par_kernel() {
    const int p = blockIdx.x;
    const int j = threadIdx.x;
    __shared__ float2 sa[2][NCHUNK];
    __shared__ float2 sb[2][NCHUNK];

    float2 a = g_lamT[p];
    float2 b = g_carry[j * PDIM + p];
    int cur = 0;
    sa[0][j] = a;
    sb[0][j] = b;
    __syncthreads();

#pragma unroll
    for (int s = 1; s < NCHUNK; s <<= 1) {
        float2 na = a, nb = b;
        if (j >= s) {
            const float2 pa = sa[cur][j - s];
            const float2 pb = sb[cur][j - s];
            na.x = a.x * pa.x - a.y * pa.y;
            na.y = a.x * pa.y + a.y * pa.x;
            nb.x = a.x * pb.x - a.y * pb.y + b.x;
            nb.y = a.x * pb.y + a.y * pb.x + b.y;
        }
        cur ^= 1;
        sa[cur][j] = na;
        sb[cur][j] = nb;
        a = na;
        b = nb;
        __syncthreads();
    }
    g_pfx[j * PDIM + p] = (j == 0) ? make_float2(0.0f, 0.0f) : sb[cur][j - 1];
}

// ---------------------------------------------------------------------------
extern "C" void kernel_launch(void* const* d_in, const int* in_sizes, int n_in,
                              void* d_out, int out_size) {
    const float* Lre     = (const float*)d_in[0];
    const float* Lim     = (const float*)d_in[1];
    const float* B       = (const float*)d_in[2];
    const float* C       = (const float*)d_in[3];
    const float* D       = (const float*)d_in[4];
    const float* logstep = (const float*)d_in[5];
    const float* u       = (const float*)d_in[6];
    float* y = (float*)d_out;

    cudaFuncSetAttribute(gemm_hmma_kernel<0>, cudaFuncAttributeMaxDynamicSharedMemorySize, SM_TOTAL);
    cudaFuncSetAttribute(gemm_hmma_kernel<1>, cudaFuncAttributeMaxDynamicSharedMemorySize, SM_TOTAL);

    prep_kernel<<<PDIM, HDIM>>>(Lre, Lim, B, C, logstep);

    dim3 grid(2, LSEQ / 128);
    gemm_hmma_kernel<0><<<grid, 256, SM_TOTAL>>>(u, nullptr, nullptr);
    carry_scan_par_kernel<<<PDIM, NCHUNK>>>();
    gemm_hmma_kernel<1><<<grid, 256, SM_TOTAL>>>(u, y, D);
}